// round 14
// baseline (speedup 1.0000x reference)
#include <cuda_runtime.h>
#include <math.h>

#define NN   8192
#define KK   200
#define CINc 512
#define HIDc 256
#define COUTc 40
#define EE   5
#define MHc  64
#define KGc  40

// ---------------- scratch (static device globals: no allocation) ----------
__device__ float g_P[KK * CINc];        // 400 KB   P = U^T X
__device__ float g_Q[KK * HIDc];        // 200 KB   Q = diag(s) (P @ Ww)
__device__ float g_A[EE * 65 * MHc];    // interval slope coeffs
__device__ float g_B[EE * 65 * MHc];    // interval intercept coeffs
__device__ float g_T[EE * MHc];         // sorted thresholds
__device__ float g_Vsum[KK];
__device__ float g_s[KK];
__device__ float g_mu[HIDc];
__device__ float g_sq[HIDc];

// ---------------- K0: zero accumulators -----------------------------------
__global__ void k_zero() {
    int i = blockIdx.x * 256 + threadIdx.x;
    if (i < KK * CINc) g_P[i] = 0.f;
    int j = i - KK * CINc;
    if (j >= 0 && j < KK) g_Vsum[j] = 0.f;
    j -= KK;
    if (j >= 0 && j < HIDc) g_mu[j] = 0.f;
    j -= HIDc;
    if (j >= 0 && j < HIDc) g_sq[j] = 0.f;
}

// ---------------- K1: piecewise-linear expert setup ------------------------
// f_e(x) = sum_g relu(x*A_g(j) + B_g(j)) * w3_g + b3,  j = interval of x
__global__ void k_setup(const float* __restrict__ eW1, const float* __restrict__ eb1,
                        const float* __restrict__ eW2, const float* __restrict__ eb2) {
    int e = blockIdx.x;
    int h = threadIdx.x;                      // 64 threads
    __shared__ float sw[64], sb[64], st[64];
    __shared__ int   sidx[64];
    float w = eW1[e * 64 + h];
    float b = eb1[e * 64 + h];
    sw[h] = w; sb[h] = b;
    st[h] = -b / w;
    __syncthreads();
    float t = st[h];
    int rank = 0;
    for (int i = 0; i < 64; i++) {
        float ti = st[i];
        rank += (ti < t) || (ti == t && i < h);
    }
    sidx[rank] = h;
    __syncthreads();
    g_T[e * 64 + h] = st[sidx[h]];
    int g = h;
    float A = 0.f, B = eb2[e * 64 + g];
    for (int p = 0; p < 64; p++) {
        if (sw[p] < 0.f) {
            float w2 = eW2[(e * 64 + p) * 64 + g];
            A += sw[p] * w2;
            B += sb[p] * w2;
        }
    }
    g_A[(e * 65 + 0) * 64 + g] = A;
    g_B[(e * 65 + 0) * 64 + g] = B;
    for (int j = 1; j <= 64; j++) {
        int p = sidx[j - 1];
        float w2 = eW2[(e * 64 + p) * 64 + g];
        float sgn = (sw[p] > 0.f) ? 1.f : -1.f;
        A += sgn * sw[p] * w2;
        B += sgn * sb[p] * w2;
        g_A[(e * 65 + j) * 64 + g] = A;
        g_B[(e * 65 + j) * 64 + g] = B;
    }
}

// ---------------- K2: evaluate experts, accumulate V sums ------------------
// grid (28, 5): wave-balanced (<=148 blocks), element-strided loop
__global__ __launch_bounds__(256) void k_expert(const float* __restrict__ U,
                         const float* __restrict__ eW3, const float* __restrict__ eb3) {
    int e = blockIdx.y;
    __shared__ float  Ts[64];
    __shared__ float2 ABs[65 * 65];
    __shared__ float  w3s[64];
    __shared__ float  Vs[KGc];
    int tid = threadIdx.x;
    for (int i = tid; i < 65 * 64; i += 256) {
        int j = i >> 6, g = i & 63;
        ABs[j * 65 + g] = make_float2(g_A[(e * 65 + j) * 64 + g],
                                      g_B[(e * 65 + j) * 64 + g]);
    }
    if (tid < 64) { Ts[tid] = g_T[e * 64 + tid]; w3s[tid] = eW3[e * 64 + tid]; }
    if (tid < KGc) Vs[tid] = 0.f;
    __syncthreads();
    float b3 = eb3[e];
    const int total = NN * KGc;
    for (int m = blockIdx.x * 256 + tid; m < total; m += 28 * 256) {
        int n = m / KGc, kg = m - n * KGc;
        float x = U[n * KK + e * KGc + kg];
        int j = 0;
        #pragma unroll
        for (int step = 64; step >= 1; step >>= 1) {
            int nj = j + step;
            if (nj <= 64 && Ts[nj - 1] < x) j = nj;
        }
        float v = b3;
        const float2* row = &ABs[j * 65];
        #pragma unroll 8
        for (int g = 0; g < 64; g++) {
            float2 ab = row[g];
            v += fmaxf(fmaf(x, ab.x, ab.y), 0.f) * w3s[g];
        }
        atomicAdd(&Vs[kg], v);
    }
    __syncthreads();
    if (tid < KGc) atomicAdd(&g_Vsum[e * KGc + tid], Vs[tid]);
}

// ---------------- K3: gate MLP + per-column scale s ------------------------
__global__ void k_gate(const float* __restrict__ La,
                       const float* __restrict__ gW1, const float* __restrict__ gb1,
                       const float* __restrict__ gW2, const float* __restrict__ gb2) {
    __shared__ float la[KK];
    __shared__ float stats[EE], z1[EE], gg[EE];
    int tid = threadIdx.x;
    if (tid < KK) la[tid] = La[tid];          // parallel DRAM load (was serial!)
    __syncthreads();
    if (tid < EE) {
        float s = 0.f;
        for (int i = 0; i < KGc; i++) s += la[tid * KGc + i];
        stats[tid] = s / (float)KGc;
    }
    __syncthreads();
    if (tid < EE) {
        float z = gb1[tid];
        for (int i = 0; i < EE; i++) z = fmaf(stats[i], gW1[i * EE + tid], z);
        z1[tid] = fmaxf(z, 0.f);
    }
    __syncthreads();
    if (tid < EE) {
        float z = gb2[tid];
        for (int i = 0; i < EE; i++) z = fmaf(z1[i], gW2[i * EE + tid], z);
        gg[tid] = z;
    }
    __syncthreads();
    if (tid == 0) {
        float m = gg[0];
        for (int i = 1; i < EE; i++) m = fmaxf(m, gg[i]);
        float se = 0.f;
        for (int i = 0; i < EE; i++) { gg[i] = expf(gg[i] - m); se += gg[i]; }
        float inv = 1.f / se;
        for (int i = 0; i < EE; i++) gg[i] *= inv;
    }
    __syncthreads();
    if (tid < KK) {
        int e = tid / KGc;
        g_s[tid] = gg[e] * (g_Vsum[tid] * (1.f / (float)NN));
    }
}

// ---------------- K4: P = U^T @ X  (200x512, reduce over 8192) -------------
// grid (2 c-tiles of 256, 5 k-tiles of 40, 14 splits) = 140 blocks (one wave)
// thread tile 5k x 8c, 256 threads
__global__ __launch_bounds__(256) void k_utx(const float* __restrict__ U,
                                             const float* __restrict__ X) {
    __shared__ float Us[32 * 41];
    __shared__ __align__(16) float Xs[32 * 260];
    int tid = threadIdx.x;
    int tx = tid & 31;        // 32 c-groups of 8
    int ty = tid >> 5;        // 8 k-groups of 5
    int c0 = blockIdx.x * 256, k0 = blockIdx.y * 40;
    float acc[5][8] = {};
    for (int ch = blockIdx.z; ch < 256; ch += 14) {
        int n0 = ch * 32;
        {
            int r = tid >> 3, k = tid & 7;
            #pragma unroll
            for (int i = 0; i < 5; i++)
                Us[r * 41 + k + i * 8] = U[(n0 + r) * KK + k0 + k + i * 8];
        }
        {
            int c4 = tid & 63, rr = tid >> 6;
            #pragma unroll
            for (int i = 0; i < 8; i++) {
                int row = rr + i * 4;
                *(float4*)&Xs[row * 260 + c4 * 4] =
                    *(const float4*)&X[(n0 + row) * CINc + c0 + c4 * 4];
            }
        }
        __syncthreads();
        #pragma unroll 2
        for (int n = 0; n < 32; n++) {
            float a[5];
            #pragma unroll
            for (int i = 0; i < 5; i++) a[i] = Us[n * 41 + ty * 5 + i];
            float4 b0 = *(const float4*)&Xs[n * 260 + tx * 8];
            float4 b1 = *(const float4*)&Xs[n * 260 + tx * 8 + 4];
            #pragma unroll
            for (int i = 0; i < 5; i++) {
                acc[i][0] = fmaf(a[i], b0.x, acc[i][0]);
                acc[i][1] = fmaf(a[i], b0.y, acc[i][1]);
                acc[i][2] = fmaf(a[i], b0.z, acc[i][2]);
                acc[i][3] = fmaf(a[i], b0.w, acc[i][3]);
                acc[i][4] = fmaf(a[i], b1.x, acc[i][4]);
                acc[i][5] = fmaf(a[i], b1.y, acc[i][5]);
                acc[i][6] = fmaf(a[i], b1.z, acc[i][6]);
                acc[i][7] = fmaf(a[i], b1.w, acc[i][7]);
            }
        }
        __syncthreads();
    }
    #pragma unroll
    for (int i = 0; i < 5; i++)
        #pragma unroll
        for (int j = 0; j < 8; j++)
            atomicAdd(&g_P[(k0 + ty * 5 + i) * CINc + c0 + tx * 8 + j], acc[i][j]);
}

// ---------------- K5: Q = diag(s) * (P @ Ww)  (200x256) --------------------
// grid (25 k-tiles of 8, 2 h-halves of 128), 128 threads
__global__ __launch_bounds__(128) void k_pq(const float* __restrict__ Ww) {
    __shared__ __align__(16) float Ps[8 * CINc];   // 16 KB
    int tid = threadIdx.x;
    int k0 = blockIdx.x * 8, h0 = blockIdx.y * 128;
    const float4* src = (const float4*)&g_P[k0 * CINc];
    float4* dst = (float4*)Ps;
    for (int i = tid; i < 8 * CINc / 4; i += 128) dst[i] = src[i];
    __syncthreads();
    int h = h0 + tid;
    float acc[8] = {};
    #pragma unroll 4
    for (int c = 0; c < CINc; c++) {
        float w = Ww[c * HIDc + h];
        #pragma unroll
        for (int r = 0; r < 8; r++) acc[r] = fmaf(Ps[r * CINc + c], w, acc[r]);
    }
    #pragma unroll
    for (int r = 0; r < 8; r++)
        g_Q[(k0 + r) * HIDc + h] = acc[r] * g_s[k0 + r];
}

// ---------------- K6: hidden = U @ Q + Wb, fused BN stats ------------------
// M=8192, N=256, K=200. tile 128x128, thread 8x8, double-buffered.
__global__ __launch_bounds__(256) void k_hid(const float* __restrict__ U,
                                             const float* __restrict__ Wb,
                                             float* __restrict__ hid) {
    __shared__ __align__(16) float As[2][8 * 132];
    __shared__ __align__(16) float Bs[2][8 * 128];
    __shared__ float bsum[128], bsq[128];
    int tid = threadIdx.x;
    int tx = tid & 15, ty = tid >> 4;
    int m0 = blockIdx.y * 128, c0 = blockIdx.x * 128;
    int rA = tid >> 1, kqA = (tid & 1) * 4;
    int kkB = tid >> 5, c4B = tid & 31;
    float4 aReg = *(const float4*)&U[(m0 + rA) * KK + kqA];
    float4 bReg = *(const float4*)&g_Q[kkB * HIDc + c0 + c4B * 4];
    As[0][(kqA + 0) * 132 + rA] = aReg.x;
    As[0][(kqA + 1) * 132 + rA] = aReg.y;
    As[0][(kqA + 2) * 132 + rA] = aReg.z;
    As[0][(kqA + 3) * 132 + rA] = aReg.w;
    *(float4*)&Bs[0][kkB * 128 + c4B * 4] = bReg;
    __syncthreads();
    float acc[8][8] = {};
    for (int step = 0; step < 25; step++) {
        int buf = step & 1;
        if (step < 24) {
            int k0 = (step + 1) * 8;
            aReg = *(const float4*)&U[(m0 + rA) * KK + k0 + kqA];
            bReg = *(const float4*)&g_Q[(k0 + kkB) * HIDc + c0 + c4B * 4];
        }
        #pragma unroll
        for (int kk = 0; kk < 8; kk++) {
            float4 a0 = *(const float4*)&As[buf][kk * 132 + ty * 8];
            float4 a1 = *(const float4*)&As[buf][kk * 132 + ty * 8 + 4];
            float4 b0 = *(const float4*)&Bs[buf][kk * 128 + tx * 8];
            float4 b1 = *(const float4*)&Bs[buf][kk * 128 + tx * 8 + 4];
            float av[8] = {a0.x, a0.y, a0.z, a0.w, a1.x, a1.y, a1.z, a1.w};
            float bv[8] = {b0.x, b0.y, b0.z, b0.w, b1.x, b1.y, b1.z, b1.w};
            #pragma unroll
            for (int i = 0; i < 8; i++)
                #pragma unroll
                for (int j = 0; j < 8; j++)
                    acc[i][j] = fmaf(av[i], bv[j], acc[i][j]);
        }
        if (step < 24) {
            int nb = buf ^ 1;
            As[nb][(kqA + 0) * 132 + rA] = aReg.x;
            As[nb][(kqA + 1) * 132 + rA] = aReg.y;
            As[nb][(kqA + 2) * 132 + rA] = aReg.z;
            As[nb][(kqA + 3) * 132 + rA] = aReg.w;
            *(float4*)&Bs[nb][kkB * 128 + c4B * 4] = bReg;
        }
        __syncthreads();
    }
    if (tid < 128) { bsum[tid] = 0.f; bsq[tid] = 0.f; }
    __syncthreads();
    float4 wb0 = *(const float4*)&Wb[c0 + tx * 8];
    float4 wb1 = *(const float4*)&Wb[c0 + tx * 8 + 4];
    float wbv[8] = {wb0.x, wb0.y, wb0.z, wb0.w, wb1.x, wb1.y, wb1.z, wb1.w};
    float cs[8] = {}, cq[8] = {};
    #pragma unroll
    for (int i = 0; i < 8; i++) {
        int row = m0 + ty * 8 + i;
        float h[8];
        #pragma unroll
        for (int j = 0; j < 8; j++) {
            h[j] = acc[i][j] + wbv[j];
            cs[j] += h[j];
            cq[j] = fmaf(h[j], h[j], cq[j]);
        }
        float4 o0 = make_float4(h[0], h[1], h[2], h[3]);
        float4 o1 = make_float4(h[4], h[5], h[6], h[7]);
        *(float4*)&hid[row * HIDc + c0 + tx * 8]     = o0;
        *(float4*)&hid[row * HIDc + c0 + tx * 8 + 4] = o1;
    }
    #pragma unroll
    for (int j = 0; j < 8; j++) {
        atomicAdd(&bsum[tx * 8 + j], cs[j]);
        atomicAdd(&bsq[tx * 8 + j], cq[j]);
    }
    __syncthreads();
    if (tid < 128) {
        atomicAdd(&g_mu[c0 + tid], bsum[tid]);
        atomicAdd(&g_sq[c0 + tid], bsq[tid]);
    }
}

// ---------------- K7: BN + ReLU + logits + log_softmax ---------------------
// 256 threads = 8 warps; warp processes 8 rows in 2 batches of 4 (shfl h-bcast)
__global__ __launch_bounds__(256)
void k_head(const float* __restrict__ hid,
            const float* __restrict__ gamma, const float* __restrict__ beta,
            const float* __restrict__ Mw, const float* __restrict__ Mb,
            float* __restrict__ outLS) {
    __shared__ float Mws[HIDc * COUTc];       // 40 KB
    __shared__ float scl[HIDc], sft[HIDc];
    int tid = threadIdx.x;
    {
        const float4* s4 = (const float4*)Mw;
        float4* d4 = (float4*)Mws;
        for (int i = tid; i < HIDc * COUTc / 4; i += 256) d4[i] = s4[i];
    }
    for (int c = tid; c < HIDc; c += 256) {
        float mean = g_mu[c] * (1.f / (float)NN);
        float var  = g_sq[c] * (1.f / (float)NN) - mean * mean;
        float sc   = rsqrtf(var + 1e-5f) * gamma[c];
        scl[c] = sc;
        sft[c] = beta[c] - mean * sc;
    }
    __syncthreads();
    int w = tid >> 5, lane = tid & 31;
    float sreg[8], oreg[8];
    #pragma unroll
    for (int u = 0; u < 8; u++) { sreg[u] = scl[lane * 8 + u]; oreg[u] = sft[lane * 8 + u]; }
    int o1 = lane, o2 = lane + 32;
    float mb1 = Mb[o1];
    float mb2 = (lane < 8) ? Mb[o2] : 0.f;
    for (int b = 0; b < 2; b++) {
        int rowbase = blockIdx.x * 64 + w * 8 + b * 4;
        float hreg[4][8];
        #pragma unroll
        for (int r = 0; r < 4; r++) {
            float4 v0 = *(const float4*)&hid[(rowbase + r) * HIDc + lane * 8];
            float4 v1 = *(const float4*)&hid[(rowbase + r) * HIDc + lane * 8 + 4];
            float vv[8] = {v0.x, v0.y, v0.z, v0.w, v1.x, v1.y, v1.z, v1.w};
            #pragma unroll
            for (int u = 0; u < 8; u++)
                hreg[r][u] = fmaxf(fmaf(vv[u], sreg[u], oreg[u]), 0.f);
        }
        float acc1[4] = {mb1, mb1, mb1, mb1};
        float acc2[4] = {mb2, mb2, mb2, mb2};
        for (int c8 = 0; c8 < 32; c8++) {
            #pragma unroll
            for (int u = 0; u < 8; u++) {
                int c = c8 * 8 + u;
                float w1 = Mws[c * COUTc + o1];
                float w2 = (lane < 8) ? Mws[c * COUTc + o2] : 0.f;
                #pragma unroll
                for (int r = 0; r < 4; r++) {
                    float hv = __shfl_sync(0xffffffffu, hreg[r][u], c8);
                    acc1[r] = fmaf(hv, w1, acc1[r]);
                    acc2[r] = fmaf(hv, w2, acc2[r]);
                }
            }
        }
        #pragma unroll
        for (int r = 0; r < 4; r++) {
            float m = (lane < 8) ? fmaxf(acc1[r], acc2[r]) : acc1[r];
            #pragma unroll
            for (int off = 16; off >= 1; off >>= 1)
                m = fmaxf(m, __shfl_xor_sync(0xffffffffu, m, off));
            float se = expf(acc1[r] - m) + ((lane < 8) ? expf(acc2[r] - m) : 0.f);
            #pragma unroll
            for (int off = 16; off >= 1; off >>= 1)
                se += __shfl_xor_sync(0xffffffffu, se, off);
            float ls = m + logf(se);
            int row = rowbase + r;
            outLS[row * COUTc + o1] = acc1[r] - ls;
            if (lane < 8) outLS[row * COUTc + o2] = acc2[r] - ls;
        }
    }
}

// ---------------- launch ----------------------------------------------------
extern "C" void kernel_launch(void* const* d_in, const int* in_sizes, int n_in,
                              void* d_out, int out_size) {
    const float* X    = (const float*)d_in[0];
    const float* La   = (const float*)d_in[1];
    const float* U    = (const float*)d_in[2];
    const float* eW1  = (const float*)d_in[3];
    const float* eb1  = (const float*)d_in[4];
    const float* eW2  = (const float*)d_in[5];
    const float* eb2  = (const float*)d_in[6];
    const float* eW3  = (const float*)d_in[7];
    const float* eb3  = (const float*)d_in[8];
    const float* gW1  = (const float*)d_in[9];
    const float* gb1  = (const float*)d_in[10];
    const float* gW2  = (const float*)d_in[11];
    const float* gb2  = (const float*)d_in[12];
    const float* Ww   = (const float*)d_in[13];
    const float* Wb   = (const float*)d_in[14];
    const float* bng  = (const float*)d_in[15];
    const float* bnb  = (const float*)d_in[16];
    const float* Mw   = (const float*)d_in[17];
    const float* Mb   = (const float*)d_in[18];

    float* outLS = (float*)d_out;                 // [N, COUT] log_softmax
    float* hid   = (float*)d_out + NN * COUTc;    // [N, HID] pre-BN hidden

    int zn = KK * CINc + KK + 2 * HIDc;
    k_zero<<<(zn + 255) / 256, 256>>>();
    k_setup<<<EE, 64>>>(eW1, eb1, eW2, eb2);
    k_expert<<<dim3(28, EE), 256>>>(U, eW3, eb3);
    k_gate<<<1, 256>>>(La, gW1, gb1, gW2, gb2);
    k_utx<<<dim3(2, 5, 14), 256>>>(U, X);
    k_pq<<<dim3(25, 2), 128>>>(Ww);
    k_hid<<<dim3(2, 64), 256>>>(U, Wb, hid);
    k_head<<<128, 256>>>(hid, bng, bnb, Mw, Mb, outLS);
}

// round 16
// speedup vs baseline: 1.1259x; 1.1259x over previous
#include <cuda_runtime.h>
#include <cuda_bf16.h>
#include <mma.h>
#include <math.h>
#include <stdint.h>

using namespace nvcuda;

#define NN   8192
#define KK   200
#define CINc 512
#define HIDc 256
#define COUTc 40
#define EE   5
#define KGc  40
#define NSPLIT 16

// ---------------- scratch (static device globals, zero-initialized) --------
__device__ __align__(16) float g_Pp[NSPLIT * 256 * 512];       // 8.4 MB split-K partials
__device__ __align__(16) __nv_bfloat16 g_Ut_hi[256 * 8192];    // U^T (rows 200+ zero)
__device__ __align__(16) __nv_bfloat16 g_Ut_lo[256 * 8192];
__device__ __align__(16) __nv_bfloat16 g_Xt_hi[512 * 8192];    // X^T
__device__ __align__(16) __nv_bfloat16 g_Xt_lo[512 * 8192];
__device__ __align__(16) __nv_bfloat16 g_Un_hi[8192 * 256];    // U row-major (col 200 = 1.0 bias)
__device__ __align__(16) __nv_bfloat16 g_Un_lo[8192 * 256];
__device__ __align__(16) __nv_bfloat16 g_Qt_hi[256 * 256];     // Q^T rows=h (col 200 = Wb)
__device__ __align__(16) __nv_bfloat16 g_Qt_lo[256 * 256];
__device__ float g_A[EE * 65 * 64];
__device__ float g_B[EE * 65 * 64];
__device__ float g_T[EE * 64];
__device__ float g_Vsum[KK];
__device__ float g_gate[EE];
__device__ float g_mu[HIDc];
__device__ float g_sq[HIDc];

__device__ __forceinline__ void split_bf16(float v, __nv_bfloat16& hi, __nv_bfloat16& lo) {
    hi = __float2bfloat16_rn(v);
    lo = __float2bfloat16_rn(v - __bfloat162float(hi));
}

// ---------------- K_init: zero tiny accumulators ----------------------------
__global__ void k_init() {
    int i = threadIdx.x;
    if (i < KK) g_Vsum[i] = 0.f;
    g_mu[i] = 0.f;
    g_sq[i] = 0.f;
}

// ---------------- K_setup: expert piecewise tables + gate -------------------
__global__ void k_setup(const float* __restrict__ eW1, const float* __restrict__ eb1,
                        const float* __restrict__ eW2, const float* __restrict__ eb2,
                        const float* __restrict__ La,
                        const float* __restrict__ gW1, const float* __restrict__ gb1,
                        const float* __restrict__ gW2, const float* __restrict__ gb2) {
    int tid = threadIdx.x;                        // 256
    if (blockIdx.x == EE) {                       // gate block (depends only on La)
        __shared__ float la[KK], stats[EE], z1[EE], gg[EE];
        if (tid < KK) la[tid] = La[tid];
        __syncthreads();
        if (tid < EE) {
            float s = 0.f;
            for (int i = 0; i < KGc; i++) s += la[tid * KGc + i];
            stats[tid] = s / (float)KGc;
        }
        __syncthreads();
        if (tid < EE) {
            float z = gb1[tid];
            for (int i = 0; i < EE; i++) z = fmaf(stats[i], gW1[i * EE + tid], z);
            z1[tid] = fmaxf(z, 0.f);
        }
        __syncthreads();
        if (tid < EE) {
            float z = gb2[tid];
            for (int i = 0; i < EE; i++) z = fmaf(z1[i], gW2[i * EE + tid], z);
            gg[tid] = z;
        }
        __syncthreads();
        if (tid == 0) {
            float m = gg[0];
            for (int i = 1; i < EE; i++) m = fmaxf(m, gg[i]);
            float se = 0.f;
            for (int i = 0; i < EE; i++) { gg[i] = expf(gg[i] - m); se += gg[i]; }
            float inv = 1.f / se;
            for (int i = 0; i < EE; i++) g_gate[i] = gg[i] * inv;
        }
        return;
    }
    int e = blockIdx.x;
    int h = tid;
    __shared__ float sw[64], sb[64], st[64];
    __shared__ int   sidx[64];
    if (h < 64) {
        float w = eW1[e * 64 + h], b = eb1[e * 64 + h];
        sw[h] = w; sb[h] = b; st[h] = -b / w;
    }
    __syncthreads();
    if (h < 64) {
        float t = st[h];
        int rank = 0;
        for (int i = 0; i < 64; i++) {
            float ti = st[i];
            rank += (ti < t) || (ti == t && i < h);
        }
        sidx[rank] = h;
    }
    __syncthreads();
    if (h < 64) {
        g_T[e * 64 + h] = st[sidx[h]];
        int g = h;
        float A = 0.f, B = eb2[e * 64 + g];
        for (int p = 0; p < 64; p++) {
            if (sw[p] < 0.f) {
                float w2 = eW2[(e * 64 + p) * 64 + g];
                A += sw[p] * w2;
                B += sb[p] * w2;
            }
        }
        g_A[(e * 65 + 0) * 64 + g] = A;
        g_B[(e * 65 + 0) * 64 + g] = B;
        for (int j = 1; j <= 64; j++) {
            int p = sidx[j - 1];
            float w2 = eW2[(e * 64 + p) * 64 + g];
            float sgn = (sw[p] > 0.f) ? 1.f : -1.f;
            A += sgn * sw[p] * w2;
            B += sgn * sb[p] * w2;
            g_A[(e * 65 + j) * 64 + g] = A;
            g_B[(e * 65 + j) * 64 + g] = B;
        }
    }
}

// ---------------- K_convU: U -> Un_hi/lo + Ut_hi/lo (transpose) -------------
__global__ __launch_bounds__(256) void k_convU(const float* __restrict__ U) {
    __shared__ float T[KGc][65];
    int tid = threadIdx.x;
    int n0 = blockIdx.x * 64, k0 = blockIdx.y * 40;
    #pragma unroll
    for (int i = 0; i < 10; i++) {
        int idx = tid + i * 256;            // 2560 elems = 64 rows x 40 k
        int r = idx / 40, c = idx - (idx / 40) * 40;
        float v = U[(n0 + r) * KK + k0 + c];
        __nv_bfloat16 hi, lo; split_bf16(v, hi, lo);
        g_Un_hi[(size_t)(n0 + r) * 256 + k0 + c] = hi;
        g_Un_lo[(size_t)(n0 + r) * 256 + k0 + c] = lo;
        T[c][r] = v;
    }
    // bias column: Un[:,200] = 1.0 so hidden = U@Q picks up Wb from Qt[:,200]
    if (blockIdx.y == 0 && tid < 64)
        g_Un_hi[(size_t)(n0 + tid) * 256 + 200] = __float2bfloat16(1.f);
    __syncthreads();
    #pragma unroll
    for (int i = 0; i < 10; i++) {
        int idx = tid + i * 256;
        int c = idx >> 6, r = idx & 63;
        float v = T[c][r];
        __nv_bfloat16 hi, lo; split_bf16(v, hi, lo);
        g_Ut_hi[(size_t)(k0 + c) * 8192 + n0 + r] = hi;
        g_Ut_lo[(size_t)(k0 + c) * 8192 + n0 + r] = lo;
    }
}

// ---------------- K_convX: X -> Xt_hi/lo (transpose) ------------------------
__global__ __launch_bounds__(256) void k_convX(const float* __restrict__ X) {
    __shared__ float T[64][65];
    int tid = threadIdx.x;
    int n0 = blockIdx.x * 64, c0 = blockIdx.y * 64;
    int r = tid >> 2, cq = (tid & 3) * 16;
    #pragma unroll
    for (int q = 0; q < 4; q++) {
        float4 v = *(const float4*)&X[(size_t)(n0 + r) * CINc + c0 + cq + q * 4];
        T[r][cq + q * 4 + 0] = v.x;
        T[r][cq + q * 4 + 1] = v.y;
        T[r][cq + q * 4 + 2] = v.z;
        T[r][cq + q * 4 + 3] = v.w;
    }
    __syncthreads();
    #pragma unroll
    for (int i = 0; i < 16; i++) {
        int idx = tid + i * 256;
        int c = idx >> 6, rr = idx & 63;
        float v = T[rr][c];
        __nv_bfloat16 hi, lo; split_bf16(v, hi, lo);
        g_Xt_hi[(size_t)(c0 + c) * 8192 + n0 + rr] = hi;
        g_Xt_lo[(size_t)(c0 + c) * 8192 + n0 + rr] = lo;
    }
}

// ---------------- K_expert: evaluate experts, accumulate V sums -------------
__global__ __launch_bounds__(256) void k_expert(const float* __restrict__ U,
                         const float* __restrict__ eW3, const float* __restrict__ eb3) {
    int e = blockIdx.y;
    __shared__ float  Ts[64];
    __shared__ float2 ABs[65 * 65];
    __shared__ float  w3s[64];
    __shared__ float  Vs[KGc];
    int tid = threadIdx.x;
    for (int i = tid; i < 65 * 64; i += 256) {
        int j = i >> 6, g = i & 63;
        ABs[j * 65 + g] = make_float2(g_A[(e * 65 + j) * 64 + g],
                                      g_B[(e * 65 + j) * 64 + g]);
    }
    if (tid < 64) { Ts[tid] = g_T[e * 64 + tid]; w3s[tid] = eW3[e * 64 + tid]; }
    if (tid < KGc) Vs[tid] = 0.f;
    __syncthreads();
    float b3 = eb3[e];
    const int total = NN * KGc, stride = 28 * 256;
    int base = blockIdx.x * 256 + tid;
    float acc[5] = {0.f, 0.f, 0.f, 0.f, 0.f};
    int t5 = 0;
    for (int m = base; m < total; m += stride) {
        int n = m / KGc, kg = m - n * KGc;
        float x = U[n * KK + e * KGc + kg];
        int j = 0;
        #pragma unroll
        for (int step = 64; step >= 1; step >>= 1) {
            int nj = j + step;
            if (nj <= 64 && Ts[nj - 1] < x) j = nj;
        }
        float v = b3;
        const float2* row = &ABs[j * 65];
        #pragma unroll 8
        for (int g = 0; g < 64; g++) {
            float2 ab = row[g];
            v += fmaxf(fmaf(x, ab.x, ab.y), 0.f) * w3s[g];
        }
        acc[t5] += v;
        if (++t5 == 5) t5 = 0;
    }
    #pragma unroll
    for (int i = 0; i < 5; i++)
        atomicAdd(&Vs[(base + 8 * i) % KGc], acc[i]);
    __syncthreads();
    if (tid < KGc) atomicAdd(&g_Vsum[e * KGc + tid], Vs[tid]);
}

// ---------------- K_mma_utx: P partials = Ut' @ Xt'^T (wmma bf16) -----------
// grid (4 n-tiles, 2 m-tiles, 16 splits), 256 threads = 8 warps (4m x 2n).
// K-tripled split: K_total = 3*8192, each split covers 1536 (48 chunks of 32).
__global__ __launch_bounds__(256) void k_mma_utx() {
    __shared__ __align__(16) __nv_bfloat16 sb[2][2][128 * 48];   // [A/B][buf], 48 KB
    int tid = threadIdx.x;
    int warp = tid >> 5;
    int wm = warp >> 1, wn = warp & 1;
    int n0 = blockIdx.x * 128, m0 = blockIdx.y * 128, split = blockIdx.z;
    const int CH = 48;
    wmma::fragment<wmma::accumulator, 16, 16, 16, float> acc[2][4];
    #pragma unroll
    for (int i = 0; i < 2; i++)
        #pragma unroll
        for (int j = 0; j < 4; j++) wmma::fill_fragment(acc[i][j], 0.f);

    int lrow = tid >> 2, lseg = (tid & 3) * 8;

    const __nv_bfloat16 *Ag, *Bg;
    {
        int g = split * 1536;
        int t = g >> 13, off = g & 8191;
        Ag = (t < 2 ? g_Ut_hi : g_Ut_lo) + (size_t)m0 * 8192 + off;
        Bg = (t == 1 ? g_Xt_lo : g_Xt_hi) + (size_t)n0 * 8192 + off;
        #pragma unroll
        for (int it = 0; it < 2; it++) {
            int r = lrow + it * 64;
            *(uint4*)&sb[0][0][r * 48 + lseg] = *(const uint4*)(Ag + (size_t)r * 8192 + lseg);
            *(uint4*)&sb[1][0][r * 48 + lseg] = *(const uint4*)(Bg + (size_t)r * 8192 + lseg);
        }
    }
    __syncthreads();
    for (int c = 0; c < CH; c++) {
        int buf = c & 1;
        uint4 pA[2], pB[2];
        if (c + 1 < CH) {
            int g = split * 1536 + (c + 1) * 32;
            int t = g >> 13, off = g & 8191;
            Ag = (t < 2 ? g_Ut_hi : g_Ut_lo) + (size_t)m0 * 8192 + off;
            Bg = (t == 1 ? g_Xt_lo : g_Xt_hi) + (size_t)n0 * 8192 + off;
            #pragma unroll
            for (int it = 0; it < 2; it++) {
                int r = lrow + it * 64;
                pA[it] = *(const uint4*)(Ag + (size_t)r * 8192 + lseg);
                pB[it] = *(const uint4*)(Bg + (size_t)r * 8192 + lseg);
            }
        }
        #pragma unroll
        for (int ks = 0; ks < 2; ks++) {
            wmma::fragment<wmma::matrix_a, 16, 16, 16, __nv_bfloat16, wmma::row_major> af[2];
            wmma::fragment<wmma::matrix_b, 16, 16, 16, __nv_bfloat16, wmma::col_major> bf[4];
            #pragma unroll
            for (int i = 0; i < 2; i++)
                wmma::load_matrix_sync(af[i], &sb[0][buf][(wm * 32 + i * 16) * 48 + ks * 16], 48);
            #pragma unroll
            for (int j = 0; j < 4; j++)
                wmma::load_matrix_sync(bf[j], &sb[1][buf][(wn * 64 + j * 16) * 48 + ks * 16], 48);
            #pragma unroll
            for (int i = 0; i < 2; i++)
                #pragma unroll
                for (int j = 0; j < 4; j++)
                    wmma::mma_sync(acc[i][j], af[i], bf[j], acc[i][j]);
        }
        if (c + 1 < CH) {
            int nb = buf ^ 1;
            #pragma unroll
            for (int it = 0; it < 2; it++) {
                int r = lrow + it * 64;
                *(uint4*)&sb[0][nb][r * 48 + lseg] = pA[it];
                *(uint4*)&sb[1][nb][r * 48 + lseg] = pB[it];
            }
        }
        __syncthreads();
    }
    float* D = g_Pp + ((size_t)split * 256 + m0 + wm * 32) * 512 + n0 + wn * 64;
    #pragma unroll
    for (int i = 0; i < 2; i++)
        #pragma unroll
        for (int j = 0; j < 4; j++)
            wmma::store_matrix_sync(D + (size_t)i * 16 * 512 + j * 16, acc[i][j],
                                    512, wmma::mem_row_major);
}

// ---------------- K_pq: reduce partials, Q = diag(s)(P @ Ww) -> Qt hi/lo ----
// grid (25, 2), 128 threads. Also plants Wb in Qt column 200.
__global__ __launch_bounds__(128) void k_pq(const float* __restrict__ Ww,
                                            const float* __restrict__ Wb) {
    __shared__ __align__(16) float Ps[8 * CINc];
    int tid = threadIdx.x;
    int k0 = blockIdx.x * 8, h0 = blockIdx.y * 128;
    float4 a[8] = {};
    for (int z = 0; z < NSPLIT; z++) {
        const float4* src = (const float4*)&g_Pp[((size_t)z * 256 + k0) * 512];
        #pragma unroll
        for (int j = 0; j < 8; j++) {
            float4 v = src[tid + j * 128];
            a[j].x += v.x; a[j].y += v.y; a[j].z += v.z; a[j].w += v.w;
        }
    }
    #pragma unroll
    for (int j = 0; j < 8; j++) ((float4*)Ps)[tid + j * 128] = a[j];
    __syncthreads();
    int h = h0 + tid;
    float acc[8] = {};
    #pragma unroll 4
    for (int c = 0; c < CINc; c++) {
        float w = Ww[c * HIDc + h];
        #pragma unroll
        for (int r = 0; r < 8; r++) acc[r] = fmaf(Ps[r * CINc + c], w, acc[r]);
    }
    float gv = g_gate[k0 / KGc] * (1.f / (float)NN);
    #pragma unroll
    for (int r = 0; r < 8; r++) {
        float q = acc[r] * (gv * g_Vsum[k0 + r]);
        __nv_bfloat16 hi, lo; split_bf16(q, hi, lo);
        g_Qt_hi[h * 256 + k0 + r] = hi;
        g_Qt_lo[h * 256 + k0 + r] = lo;
    }
    if (blockIdx.x == 0) {                       // bias column
        __nv_bfloat16 hi, lo; split_bf16(Wb[h], hi, lo);
        g_Qt_hi[h * 256 + 200] = hi;
        g_Qt_lo[h * 256 + 200] = lo;
    }
}

// ---------------- K_mma_hid: hidden = U @ Q (+Wb via k=200 col) (wmma) ------
// grid (2 n-tiles, 64 m-tiles), 256 threads. K_total = 3*256 = 24 chunks.
__global__ __launch_bounds__(256) void k_mma_hid(float* __restrict__ hid) {
    __shared__ __align__(16) __nv_bfloat16 sb[2][2][128 * 48];
    int tid = threadIdx.x;
    int warp = tid >> 5;
    int wm = warp >> 1, wn = warp & 1;
    int n0 = blockIdx.x * 128, m0 = blockIdx.y * 128;
    const int CH = 24;
    wmma::fragment<wmma::accumulator, 16, 16, 16, float> acc[2][4];
    #pragma unroll
    for (int i = 0; i < 2; i++)
        #pragma unroll
        for (int j = 0; j < 4; j++) wmma::fill_fragment(acc[i][j], 0.f);

    int lrow = tid >> 2, lseg = (tid & 3) * 8;

    const __nv_bfloat16 *Ag, *Bg;
    {
        Ag = g_Un_hi + (size_t)m0 * 256;
        Bg = g_Qt_hi + (size_t)n0 * 256;
        #pragma unroll
        for (int it = 0; it < 2; it++) {
            int r = lrow + it * 64;
            *(uint4*)&sb[0][0][r * 48 + lseg] = *(const uint4*)(Ag + (size_t)r * 256 + lseg);
            *(uint4*)&sb[1][0][r * 48 + lseg] = *(const uint4*)(Bg + (size_t)r * 256 + lseg);
        }
    }
    __syncthreads();
    for (int c = 0; c < CH; c++) {
        int buf = c & 1;
        uint4 pA[2], pB[2];
        if (c + 1 < CH) {
            int cn = c + 1;
            int t = cn >> 3, kc = (cn & 7) * 32;
            Ag = (t < 2 ? g_Un_hi : g_Un_lo) + (size_t)m0 * 256 + kc;
            Bg = (t == 1 ? g_Qt_lo : g_Qt_hi) + (size_t)n0 * 256 + kc;
            #pragma unroll
            for (int it = 0; it < 2; it++) {
                int r = lrow + it * 64;
                pA[it] = *(const uint4*)(Ag + (size_t)r * 256 + lseg);
                pB[it] = *(const uint4*)(Bg + (size_t)r * 256 + lseg);
            }
        }
        #pragma unroll
        for (int ks = 0; ks < 2; ks++) {
            wmma::fragment<wmma::matrix_a, 16, 16, 16, __nv_bfloat16, wmma::row_major> af[2];
            wmma::fragment<wmma::matrix_b, 16, 16, 16, __nv_bfloat16, wmma::col_major> bf[4];
            #pragma unroll
            for (int i = 0; i < 2; i++)
                wmma::load_matrix_sync(af[i], &sb[0][buf][(wm * 32 + i * 16) * 48 + ks * 16], 48);
            #pragma unroll
            for (int j = 0; j < 4; j++)
                wmma::load_matrix_sync(bf[j], &sb[1][buf][(wn * 64 + j * 16) * 48 + ks * 16], 48);
            #pragma unroll
            for (int i = 0; i < 2; i++)
                #pragma unroll
                for (int j = 0; j < 4; j++)
                    wmma::mma_sync(acc[i][j], af[i], bf[j], acc[i][j]);
        }
        if (c + 1 < CH) {
            int nb = buf ^ 1;
            #pragma unroll
            for (int it = 0; it < 2; it++) {
                int r = lrow + it * 64;
                *(uint4*)&sb[0][nb][r * 48 + lseg] = pA[it];
                *(uint4*)&sb[1][nb][r * 48 + lseg] = pB[it];
            }
        }
        __syncthreads();
    }
    float* D = hid + (size_t)(m0 + wm * 32) * 256 + n0 + wn * 64;
    #pragma unroll
    for (int i = 0; i < 2; i++)
        #pragma unroll
        for (int j = 0; j < 4; j++)
            wmma::store_matrix_sync(D + (size_t)i * 16 * 256 + j * 16, acc[i][j],
                                    256, wmma::mem_row_major);
}

// ---------------- K_bnstats --------------------------------------------------
__global__ void k_bnstats(const float* __restrict__ hid) {
    int c = threadIdx.x;
    int r0 = blockIdx.x * 32;
    float s = 0.f, sq = 0.f;
    #pragma unroll 8
    for (int i = 0; i < 32; i++) {
        float v = hid[(size_t)(r0 + i) * HIDc + c];
        s += v; sq = fmaf(v, v, sq);
    }
    atomicAdd(&g_mu[c], s);
    atomicAdd(&g_sq[c], sq);
}

// ---------------- K_head: BN + ReLU + logits + log_softmax -------------------
__global__ __launch_bounds__(256)
void k_head(const float* __restrict__ hid,
            const float* __restrict__ gamma, const float* __restrict__ beta,
            const float* __restrict__ Mw, const float* __restrict__ Mb,
            float* __restrict__ outLS) {
    __shared__ float Mws[HIDc * COUTc];
    __shared__ float scl[HIDc], sft[HIDc];
    int tid = threadIdx.x;
    {
        const float4* s4 = (const float4*)Mw;
        float4* d4 = (float4*)Mws;
        for (int i = tid; i < HIDc * COUTc / 4; i += 256) d4[i] = s4[i];
    }
    for (int c = tid; c < HIDc; c += 256) {
        float mean = g_mu[c] * (1.f / (float)NN);
        float var  = g_sq[c] * (1.f / (float)NN) - mean * mean;
        float sc   = rsqrtf(var + 1e-5f) * gamma[c];
        scl[c] = sc;
        sft[c] = beta[c] - mean * sc;
    }
    __syncthreads();
    int w = tid >> 5, lane = tid & 31;
    float sreg[8], oreg[8];
    #pragma unroll
    for (int u = 0; u < 8; u++) { sreg[u] = scl[lane * 8 + u]; oreg[u] = sft[lane * 8 + u]; }
    int o1 = lane, o2 = lane + 32;
    float mb1 = Mb[o1];
    float mb2 = (lane < 8) ? Mb[o2] : 0.f;
    for (int b = 0; b < 2; b++) {
        int rowbase = blockIdx.x * 64 + w * 8 + b * 4;
        float hreg[4][8];
        #pragma unroll
        for (int r = 0; r < 4; r++) {
            float4 v0 = *(const float4*)&hid[(size_t)(rowbase + r) * HIDc + lane * 8];
            float4 v1 = *(const float4*)&hid[(size_t)(rowbase + r) * HIDc + lane * 8 + 4];
            float vv[8] = {v0.x, v0.y, v0.z, v0.w, v1.x, v1.y, v1.z, v1.w};
            #pragma unroll
            for (int u = 0; u < 8; u++)
                hreg[r][u] = fmaxf(fmaf(vv[u], sreg[u], oreg[u]), 0.f);
        }
        float acc1[4] = {mb1, mb1, mb1, mb1};
        float acc2[4] = {mb2, mb2, mb2, mb2};
        for (int c8 = 0; c8 < 32; c8++) {
            #pragma unroll
            for (int u = 0; u < 8; u++) {
                int c = c8 * 8 + u;
                float w1 = Mws[c * COUTc + o1];
                float w2 = (lane < 8) ? Mws[c * COUTc + o2] : 0.f;
                #pragma unroll
                for (int r = 0; r < 4; r++) {
                    float hv = __shfl_sync(0xffffffffu, hreg[r][u], c8);
                    acc1[r] = fmaf(hv, w1, acc1[r]);
                    acc2[r] = fmaf(hv, w2, acc2[r]);
                }
            }
        }
        #pragma unroll
        for (int r = 0; r < 4; r++) {
            float m = (lane < 8) ? fmaxf(acc1[r], acc2[r]) : acc1[r];
            #pragma unroll
            for (int off = 16; off >= 1; off >>= 1)
                m = fmaxf(m, __shfl_xor_sync(0xffffffffu, m, off));
            float se = expf(acc1[r] - m) + ((lane < 8) ? expf(acc2[r] - m) : 0.f);
            #pragma unroll
            for (int off = 16; off >= 1; off >>= 1)
                se += __shfl_xor_sync(0xffffffffu, se, off);
            float ls = m + logf(se);
            int row = rowbase + r;
            outLS[row * COUTc + o1] = acc1[r] - ls;
            if (lane < 8) outLS[row * COUTc + o2] = acc2[r] - ls;
        }
    }
}

// ---------------- launch ------------------------------------------------------
extern "C" void kernel_launch(void* const* d_in, const int* in_sizes, int n_in,
                              void* d_out, int out_size) {
    const float* X    = (const float*)d_in[0];
    const float* La   = (const float*)d_in[1];
    const float* U    = (const float*)d_in[2];
    const float* eW1  = (const float*)d_in[3];
    const float* eb1  = (const float*)d_in[4];
    const float* eW2  = (const float*)d_in[5];
    const float* eb2  = (const float*)d_in[6];
    const float* eW3  = (const float*)d_in[7];
    const float* eb3  = (const float*)d_in[8];
    const float* gW1  = (const float*)d_in[9];
    const float* gb1  = (const float*)d_in[10];
    const float* gW2  = (const float*)d_in[11];
    const float* gb2  = (const float*)d_in[12];
    const float* Ww   = (const float*)d_in[13];
    const float* Wb   = (const float*)d_in[14];
    const float* bng  = (const float*)d_in[15];
    const float* bnb  = (const float*)d_in[16];
    const float* Mw   = (const float*)d_in[17];
    const float* Mb   = (const float*)d_in[18];

    float* outLS = (float*)d_out;
    float* hid   = (float*)d_out + NN * COUTc;

    k_init<<<1, 256>>>();
    k_setup<<<EE + 1, 256>>>(eW1, eb1, eW2, eb2, La, gW1, gb1, gW2, gb2);
    k_convU<<<dim3(128, 5), 256>>>(U);
    k_convX<<<dim3(128, 8), 256>>>(X);
    k_expert<<<dim3(28, EE), 256>>>(U, eW3, eb3);
    k_mma_utx<<<dim3(4, 2, NSPLIT), 256>>>();
    k_pq<<<dim3(25, 2), 128>>>(Ww, Wb);
    k_mma_hid<<<dim3(2, 64), 256>>>(hid);
    k_bnstats<<<256, 256>>>(hid);
    k_head<<<128, 256>>>(hid, bng, bnb, Mw, Mb, outLS);
}

// round 17
// speedup vs baseline: 1.2967x; 1.1517x over previous
#include <cuda_runtime.h>
#include <cuda_bf16.h>
#include <mma.h>
#include <math.h>
#include <stdint.h>

using namespace nvcuda;

#define NN   8192
#define KK   200
#define CINc 512
#define HIDc 256
#define COUTc 40
#define EE   5
#define KGc  40
#define NSPLIT 16

// ---------------- scratch (static device globals, zero-initialized) --------
__device__ __align__(16) float g_Pp[NSPLIT * 256 * 512];     // 8.4 MB split-K partials
__device__ __align__(16) __nv_bfloat16 g_Qn_hi[256 * 256];   // Q k-major (row 200 = Wb)
__device__ __align__(16) __nv_bfloat16 g_Qn_lo[256 * 256];
__device__ float g_A[EE * 65 * 64];
__device__ float g_B[EE * 65 * 64];
__device__ float g_T[EE * 64];
__device__ float g_Vsum[KK];
__device__ float g_gate[EE];
__device__ float g_mu[HIDc];
__device__ float g_sq[HIDc];

__device__ __forceinline__ void split_bf16(float v, __nv_bfloat16& hi, __nv_bfloat16& lo) {
    hi = __float2bfloat16_rn(v);
    lo = __float2bfloat16_rn(v - __bfloat162float(hi));
}

// ---------------- K_setup: expert tables + gate + zero-init -----------------
__global__ void k_setup(const float* __restrict__ eW1, const float* __restrict__ eb1,
                        const float* __restrict__ eW2, const float* __restrict__ eb2,
                        const float* __restrict__ La,
                        const float* __restrict__ gW1, const float* __restrict__ gb1,
                        const float* __restrict__ gW2, const float* __restrict__ gb2) {
    int tid = threadIdx.x;                        // 256
    if (blockIdx.x == EE + 1) {                   // zero-init block
        if (tid < KK) g_Vsum[tid] = 0.f;
        g_mu[tid] = 0.f;
        g_sq[tid] = 0.f;
        return;
    }
    if (blockIdx.x == EE) {                       // gate block (depends only on La)
        __shared__ float la[KK], stats[EE], z1[EE], gg[EE];
        if (tid < KK) la[tid] = La[tid];
        __syncthreads();
        if (tid < EE) {
            float s = 0.f;
            for (int i = 0; i < KGc; i++) s += la[tid * KGc + i];
            stats[tid] = s / (float)KGc;
        }
        __syncthreads();
        if (tid < EE) {
            float z = gb1[tid];
            for (int i = 0; i < EE; i++) z = fmaf(stats[i], gW1[i * EE + tid], z);
            z1[tid] = fmaxf(z, 0.f);
        }
        __syncthreads();
        if (tid < EE) {
            float z = gb2[tid];
            for (int i = 0; i < EE; i++) z = fmaf(z1[i], gW2[i * EE + tid], z);
            gg[tid] = z;
        }
        __syncthreads();
        if (tid == 0) {
            float m = gg[0];
            for (int i = 1; i < EE; i++) m = fmaxf(m, gg[i]);
            float se = 0.f;
            for (int i = 0; i < EE; i++) { gg[i] = expf(gg[i] - m); se += gg[i]; }
            float inv = 1.f / se;
            for (int i = 0; i < EE; i++) g_gate[i] = gg[i] * inv;
        }
        return;
    }
    int e = blockIdx.x;
    int h = tid;
    __shared__ float sw[64], sb[64], st[64];
    __shared__ int   sidx[64];
    if (h < 64) {
        float w = eW1[e * 64 + h], b = eb1[e * 64 + h];
        sw[h] = w; sb[h] = b; st[h] = -b / w;
    }
    __syncthreads();
    if (h < 64) {
        float t = st[h];
        int rank = 0;
        for (int i = 0; i < 64; i++) {
            float ti = st[i];
            rank += (ti < t) || (ti == t && i < h);
        }
        sidx[rank] = h;
    }
    __syncthreads();
    if (h < 64) {
        g_T[e * 64 + h] = st[sidx[h]];
        int g = h;
        float A = 0.f, B = eb2[e * 64 + g];
        for (int p = 0; p < 64; p++) {
            if (sw[p] < 0.f) {
                float w2 = eW2[(e * 64 + p) * 64 + g];
                A += sw[p] * w2;
                B += sb[p] * w2;
            }
        }
        g_A[(e * 65 + 0) * 64 + g] = A;
        g_B[(e * 65 + 0) * 64 + g] = B;
        for (int j = 1; j <= 64; j++) {
            int p = sidx[j - 1];
            float w2 = eW2[(e * 64 + p) * 64 + g];
            float sgn = (sw[p] > 0.f) ? 1.f : -1.f;
            A += sgn * sw[p] * w2;
            B += sgn * sb[p] * w2;
            g_A[(e * 65 + j) * 64 + g] = A;
            g_B[(e * 65 + j) * 64 + g] = B;
        }
    }
}

// ---------------- K_expert: evaluate experts, accumulate V sums -------------
__global__ __launch_bounds__(256) void k_expert(const float* __restrict__ U,
                         const float* __restrict__ eW3, const float* __restrict__ eb3) {
    int e = blockIdx.y;
    __shared__ float  Ts[64];
    __shared__ float2 ABs[65 * 65];
    __shared__ float  w3s[64];
    __shared__ float  Vs[KGc];
    int tid = threadIdx.x;
    for (int i = tid; i < 65 * 64; i += 256) {
        int j = i >> 6, g = i & 63;
        ABs[j * 65 + g] = make_float2(g_A[(e * 65 + j) * 64 + g],
                                      g_B[(e * 65 + j) * 64 + g]);
    }
    if (tid < 64) { Ts[tid] = g_T[e * 64 + tid]; w3s[tid] = eW3[e * 64 + tid]; }
    if (tid < KGc) Vs[tid] = 0.f;
    __syncthreads();
    float b3 = eb3[e];
    const int total = NN * KGc, stride = 28 * 256;
    int base = blockIdx.x * 256 + tid;
    float acc[5] = {0.f, 0.f, 0.f, 0.f, 0.f};
    int t5 = 0;
    for (int m = base; m < total; m += stride) {
        int n = m / KGc, kg = m - n * KGc;
        float x = U[n * KK + e * KGc + kg];
        int j = 0;
        #pragma unroll
        for (int step = 64; step >= 1; step >>= 1) {
            int nj = j + step;
            if (nj <= 64 && Ts[nj - 1] < x) j = nj;
        }
        float v = b3;
        const float2* row = &ABs[j * 65];
        #pragma unroll 8
        for (int g = 0; g < 64; g++) {
            float2 ab = row[g];
            v += fmaxf(fmaf(x, ab.x, ab.y), 0.f) * w3s[g];
        }
        acc[t5] += v;
        if (++t5 == 5) t5 = 0;
    }
    #pragma unroll
    for (int i = 0; i < 5; i++)
        atomicAdd(&Vs[(base + 8 * i) % KGc], acc[i]);
    __syncthreads();
    if (tid < KGc) atomicAdd(&g_Vsum[e * KGc + tid], Vs[tid]);
}

// ---------------- K_mma_utx: P = U^T @ X, fp32->bf16 split fused ------------
// grid (4 c-tiles, 2 m-tiles, 16 splits), 256 threads = 8 warps (4m x 2c).
// contraction n = 8192; split covers 512 n = 16 chunks of 32.
// A col_major: (m,k)=U[n=k][m]; B row_major: (k,c)=X[n=k][c].
__global__ __launch_bounds__(256) void k_mma_utx(const float* __restrict__ U,
                                                 const float* __restrict__ X) {
    __shared__ __align__(16) __nv_bfloat16 sA_hi[32][136], sA_lo[32][136];
    __shared__ __align__(16) __nv_bfloat16 sB_hi[32][136], sB_lo[32][136];
    int tid = threadIdx.x;
    int warp = tid >> 5;
    int wm = warp >> 1, wn = warp & 1;
    int c0 = blockIdx.x * 128, m0 = blockIdx.y * 128, split = blockIdx.z;
    int nbase = split * 512;
    wmma::fragment<wmma::accumulator, 16, 16, 16, float> acc[2][4];
    #pragma unroll
    for (int i = 0; i < 2; i++)
        #pragma unroll
        for (int j = 0; j < 4; j++) wmma::fill_fragment(acc[i][j], 0.f);

    int lr = tid >> 3, ls = (tid & 7) * 16;       // row-in-chunk, 16-col segment

    float va[16], vb[16];
    // prologue: load chunk 0
    {
        int n = nbase + lr;
        if (m0 + ls + 15 < KK) {
            #pragma unroll
            for (int q = 0; q < 4; q++)
                *(float4*)&va[q * 4] = *(const float4*)&U[(size_t)n * KK + m0 + ls + q * 4];
        } else {
            #pragma unroll
            for (int i = 0; i < 16; i++) {
                int gm = m0 + ls + i;
                va[i] = (gm < KK) ? U[(size_t)n * KK + gm] : 0.f;
            }
        }
        #pragma unroll
        for (int q = 0; q < 4; q++)
            *(float4*)&vb[q * 4] = *(const float4*)&X[(size_t)n * CINc + c0 + ls + q * 4];
    }
    for (int ch = 0; ch < 16; ch++) {
        if (ch) __syncthreads();                  // prior MMA reads done
        {
            alignas(16) __nv_bfloat16 ah[16], al[16], bh[16], bl[16];
            #pragma unroll
            for (int i = 0; i < 16; i++) {
                split_bf16(va[i], ah[i], al[i]);
                split_bf16(vb[i], bh[i], bl[i]);
            }
            *(uint4*)&sA_hi[lr][ls]     = *(uint4*)&ah[0];
            *(uint4*)&sA_hi[lr][ls + 8] = *(uint4*)&ah[8];
            *(uint4*)&sA_lo[lr][ls]     = *(uint4*)&al[0];
            *(uint4*)&sA_lo[lr][ls + 8] = *(uint4*)&al[8];
            *(uint4*)&sB_hi[lr][ls]     = *(uint4*)&bh[0];
            *(uint4*)&sB_hi[lr][ls + 8] = *(uint4*)&bh[8];
            *(uint4*)&sB_lo[lr][ls]     = *(uint4*)&bl[0];
            *(uint4*)&sB_lo[lr][ls + 8] = *(uint4*)&bl[8];
        }
        __syncthreads();
        if (ch + 1 < 16) {                        // prefetch next chunk (overlaps MMA)
            int n = nbase + (ch + 1) * 32 + lr;
            if (m0 + ls + 15 < KK) {
                #pragma unroll
                for (int q = 0; q < 4; q++)
                    *(float4*)&va[q * 4] = *(const float4*)&U[(size_t)n * KK + m0 + ls + q * 4];
            } else {
                #pragma unroll
                for (int i = 0; i < 16; i++) {
                    int gm = m0 + ls + i;
                    va[i] = (gm < KK) ? U[(size_t)n * KK + gm] : 0.f;
                }
            }
            #pragma unroll
            for (int q = 0; q < 4; q++)
                *(float4*)&vb[q * 4] = *(const float4*)&X[(size_t)n * CINc + c0 + ls + q * 4];
        }
        #pragma unroll
        for (int combo = 0; combo < 3; combo++) {
            const __nv_bfloat16* pA = (combo == 2) ? &sA_lo[0][0] : &sA_hi[0][0];
            const __nv_bfloat16* pB = (combo == 1) ? &sB_lo[0][0] : &sB_hi[0][0];
            #pragma unroll
            for (int ks = 0; ks < 2; ks++) {
                wmma::fragment<wmma::matrix_a, 16, 16, 16, __nv_bfloat16, wmma::col_major> af[2];
                wmma::fragment<wmma::matrix_b, 16, 16, 16, __nv_bfloat16, wmma::row_major> bf[4];
                #pragma unroll
                for (int i = 0; i < 2; i++)
                    wmma::load_matrix_sync(af[i], pA + (ks * 16) * 136 + wm * 32 + i * 16, 136);
                #pragma unroll
                for (int j = 0; j < 4; j++)
                    wmma::load_matrix_sync(bf[j], pB + (ks * 16) * 136 + wn * 64 + j * 16, 136);
                #pragma unroll
                for (int i = 0; i < 2; i++)
                    #pragma unroll
                    for (int j = 0; j < 4; j++)
                        wmma::mma_sync(acc[i][j], af[i], bf[j], acc[i][j]);
            }
        }
    }
    float* D = g_Pp + ((size_t)split * 256 + m0 + wm * 32) * 512 + c0 + wn * 64;
    #pragma unroll
    for (int i = 0; i < 2; i++)
        #pragma unroll
        for (int j = 0; j < 4; j++)
            wmma::store_matrix_sync(D + (size_t)i * 16 * 512 + j * 16, acc[i][j],
                                    512, wmma::mem_row_major);
}

// ---------------- K_pq: reduce partials, Q = diag(s)(P @ Ww) -> Qn hi/lo ----
// grid (25, 2), 128 threads. Plants Wb in Qn row 200. Qn is k-major [k][h].
__global__ __launch_bounds__(128) void k_pq(const float* __restrict__ Ww,
                                            const float* __restrict__ Wb) {
    __shared__ __align__(16) float Ps[8 * CINc];
    int tid = threadIdx.x;
    int k0 = blockIdx.x * 8, h0 = blockIdx.y * 128;
    float4 a[8] = {};
    for (int z = 0; z < NSPLIT; z++) {
        const float4* src = (const float4*)&g_Pp[((size_t)z * 256 + k0) * 512];
        #pragma unroll
        for (int j = 0; j < 8; j++) {
            float4 v = src[tid + j * 128];
            a[j].x += v.x; a[j].y += v.y; a[j].z += v.z; a[j].w += v.w;
        }
    }
    #pragma unroll
    for (int j = 0; j < 8; j++) ((float4*)Ps)[tid + j * 128] = a[j];
    __syncthreads();
    int h = h0 + tid;
    float acc[8] = {};
    #pragma unroll 4
    for (int c = 0; c < CINc; c++) {
        float w = Ww[c * HIDc + h];
        #pragma unroll
        for (int r = 0; r < 8; r++) acc[r] = fmaf(Ps[r * CINc + c], w, acc[r]);
    }
    float gv = g_gate[k0 / KGc] * (1.f / (float)NN);
    #pragma unroll
    for (int r = 0; r < 8; r++) {
        float q = acc[r] * (gv * g_Vsum[k0 + r]);
        __nv_bfloat16 hi, lo; split_bf16(q, hi, lo);
        g_Qn_hi[(k0 + r) * 256 + h] = hi;
        g_Qn_lo[(k0 + r) * 256 + h] = lo;
    }
    if (blockIdx.x == 0) {                        // bias row k=200
        __nv_bfloat16 hi, lo; split_bf16(Wb[h], hi, lo);
        g_Qn_hi[200 * 256 + h] = hi;
        g_Qn_lo[200 * 256 + h] = lo;
    }
}

// ---------------- K_mma_hid: hidden = U @ Q (+Wb) + fused BN stats ----------
// grid (2 h-tiles, 64 m-tiles), 256 threads. contraction 224 = 7 chunks of 32.
// A row_major from U fp32 (split in-kernel, bias col k=200 = 1). B = Qn global.
__global__ __launch_bounds__(256) void k_mma_hid(const float* __restrict__ U,
                                                 float* __restrict__ hid) {
    __shared__ __align__(16) __nv_bfloat16 sA_hi[128][40], sA_lo[128][40];
    __shared__ float s_sum[2][128], s_sq[2][128];
    int tid = threadIdx.x;
    int warp = tid >> 5;
    int wm = warp >> 1, wn = warp & 1;
    int h0 = blockIdx.x * 128, m0 = blockIdx.y * 128;
    wmma::fragment<wmma::accumulator, 16, 16, 16, float> acc[2][4];
    #pragma unroll
    for (int i = 0; i < 2; i++)
        #pragma unroll
        for (int j = 0; j < 4; j++) wmma::fill_fragment(acc[i][j], 0.f);

    int lr = tid >> 1, ls = (tid & 1) * 16;       // row (0..127), col segment

    for (int ch = 0; ch < 7; ch++) {
        int k0 = ch * 32;
        float v[16];
        if (k0 + ls + 15 < KK) {
            #pragma unroll
            for (int q = 0; q < 4; q++)
                *(float4*)&v[q * 4] = *(const float4*)&U[(size_t)(m0 + lr) * KK + k0 + ls + q * 4];
        } else {
            #pragma unroll
            for (int i = 0; i < 16; i++) {
                int gk = k0 + ls + i;
                v[i] = (gk < KK) ? U[(size_t)(m0 + lr) * KK + gk]
                                 : (gk == KK ? 1.f : 0.f);
            }
        }
        if (ch) __syncthreads();
        {
            alignas(16) __nv_bfloat16 hh[16], ll[16];
            #pragma unroll
            for (int i = 0; i < 16; i++) split_bf16(v[i], hh[i], ll[i]);
            *(uint4*)&sA_hi[lr][ls]     = *(uint4*)&hh[0];
            *(uint4*)&sA_hi[lr][ls + 8] = *(uint4*)&hh[8];
            *(uint4*)&sA_lo[lr][ls]     = *(uint4*)&ll[0];
            *(uint4*)&sA_lo[lr][ls + 8] = *(uint4*)&ll[8];
        }
        __syncthreads();
        #pragma unroll
        for (int combo = 0; combo < 3; combo++) {
            const __nv_bfloat16* pA = (combo == 2) ? &sA_lo[0][0] : &sA_hi[0][0];
            const __nv_bfloat16* pB = (combo == 1) ? g_Qn_lo : g_Qn_hi;
            #pragma unroll
            for (int ks = 0; ks < 2; ks++) {
                wmma::fragment<wmma::matrix_a, 16, 16, 16, __nv_bfloat16, wmma::row_major> af[2];
                wmma::fragment<wmma::matrix_b, 16, 16, 16, __nv_bfloat16, wmma::row_major> bf[4];
                #pragma unroll
                for (int i = 0; i < 2; i++)
                    wmma::load_matrix_sync(af[i], pA + (wm * 32 + i * 16) * 40 + ks * 16, 40);
                #pragma unroll
                for (int j = 0; j < 4; j++)
                    wmma::load_matrix_sync(bf[j], pB + (k0 + ks * 16) * 256 + h0 + wn * 64 + j * 16, 256);
                #pragma unroll
                for (int i = 0; i < 2; i++)
                    #pragma unroll
                    for (int j = 0; j < 4; j++)
                        wmma::mma_sync(acc[i][j], af[i], bf[j], acc[i][j]);
            }
        }
    }
    float* D = hid + (size_t)(m0 + wm * 32) * HIDc + h0 + wn * 64;
    #pragma unroll
    for (int i = 0; i < 2; i++)
        #pragma unroll
        for (int j = 0; j < 4; j++)
            wmma::store_matrix_sync(D + (size_t)i * 16 * HIDc + j * 16, acc[i][j],
                                    HIDc, wmma::mem_row_major);
    __syncthreads();
    // fused BN stats over this CTA's 128x128 tile (L2-hot re-read)
    {
        int c = tid & 127, half = tid >> 7;
        float s = 0.f, sq = 0.f;
        const float* col = hid + (size_t)(m0 + half * 64) * HIDc + h0 + c;
        #pragma unroll 8
        for (int r = 0; r < 64; r++) {
            float v = col[(size_t)r * HIDc];
            s += v; sq = fmaf(v, v, sq);
        }
        s_sum[half][c] = s;
        s_sq[half][c] = sq;
    }
    __syncthreads();
    if (tid < 128) {
        atomicAdd(&g_mu[h0 + tid], s_sum[0][tid] + s_sum[1][tid]);
        atomicAdd(&g_sq[h0 + tid], s_sq[0][tid] + s_sq[1][tid]);
    }
}

// ---------------- K_head: BN + ReLU + logits + log_softmax -------------------
__global__ __launch_bounds__(256)
void k_head(const float* __restrict__ hid,
            const float* __restrict__ gamma, const float* __restrict__ beta,
            const float* __restrict__ Mw, const float* __restrict__ Mb,
            float* __restrict__ outLS) {
    __shared__ float Mws[HIDc * COUTc];
    __shared__ float scl[HIDc], sft[HIDc];
    int tid = threadIdx.x;
    {
        const float4* s4 = (const float4*)Mw;
        float4* d4 = (float4*)Mws;
        for (int i = tid; i < HIDc * COUTc / 4; i += 256) d4[i] = s4[i];
    }
    for (int c = tid; c < HIDc; c += 256) {
        float mean = g_mu[c] * (1.f / (float)NN);
        float var  = g_sq[c] * (1.f / (float)NN) - mean * mean;
        float sc   = rsqrtf(var + 1e-5f) * gamma[c];
        scl[c] = sc;
        sft[c] = beta[c] - mean * sc;
    }
    __syncthreads();
    int w = tid >> 5, lane = tid & 31;
    float sreg[8], oreg[8];
    #pragma unroll
    for (int u = 0; u < 8; u++) { sreg[u] = scl[lane * 8 + u]; oreg[u] = sft[lane * 8 + u]; }
    int o1 = lane, o2 = lane + 32;
    float mb1 = Mb[o1];
    float mb2 = (lane < 8) ? Mb[o2] : 0.f;
    for (int b = 0; b < 2; b++) {
        int rowbase = blockIdx.x * 64 + w * 8 + b * 4;
        float hreg[4][8];
        #pragma unroll
        for (int r = 0; r < 4; r++) {
            float4 v0 = *(const float4*)&hid[(size_t)(rowbase + r) * HIDc + lane * 8];
            float4 v1 = *(const float4*)&hid[(size_t)(rowbase + r) * HIDc + lane * 8 + 4];
            float vv[8] = {v0.x, v0.y, v0.z, v0.w, v1.x, v1.y, v1.z, v1.w};
            #pragma unroll
            for (int u = 0; u < 8; u++)
                hreg[r][u] = fmaxf(fmaf(vv[u], sreg[u], oreg[u]), 0.f);
        }
        float acc1[4] = {mb1, mb1, mb1, mb1};
        float acc2[4] = {mb2, mb2, mb2, mb2};
        for (int c8 = 0; c8 < 32; c8++) {
            #pragma unroll
            for (int u = 0; u < 8; u++) {
                int c = c8 * 8 + u;
                float w1 = Mws[c * COUTc + o1];
                float w2 = (lane < 8) ? Mws[c * COUTc + o2] : 0.f;
                #pragma unroll
                for (int r = 0; r < 4; r++) {
                    float hv = __shfl_sync(0xffffffffu, hreg[r][u], c8);
                    acc1[r] = fmaf(hv, w1, acc1[r]);
                    acc2[r] = fmaf(hv, w2, acc2[r]);
                }
            }
        }
        #pragma unroll
        for (int r = 0; r < 4; r++) {
            float m = (lane < 8) ? fmaxf(acc1[r], acc2[r]) : acc1[r];
            #pragma unroll
            for (int off = 16; off >= 1; off >>= 1)
                m = fmaxf(m, __shfl_xor_sync(0xffffffffu, m, off));
            float se = expf(acc1[r] - m) + ((lane < 8) ? expf(acc2[r] - m) : 0.f);
            #pragma unroll
            for (int off = 16; off >= 1; off >>= 1)
                se += __shfl_xor_sync(0xffffffffu, se, off);
            float ls = m + logf(se);
            int row = rowbase + r;
            outLS[row * COUTc + o1] = acc1[r] - ls;
            if (lane < 8) outLS[row * COUTc + o2] = acc2[r] - ls;
        }
    }
}

// ---------------- launch ------------------------------------------------------
extern "C" void kernel_launch(void* const* d_in, const int* in_sizes, int n_in,
                              void* d_out, int out_size) {
    const float* X    = (const float*)d_in[0];
    const float* La   = (const float*)d_in[1];
    const float* U    = (const float*)d_in[2];
    const float* eW1  = (const float*)d_in[3];
    const float* eb1  = (const float*)d_in[4];
    const float* eW2  = (const float*)d_in[5];
    const float* eb2  = (const float*)d_in[6];
    const float* eW3  = (const float*)d_in[7];
    const float* eb3  = (const float*)d_in[8];
    const float* gW1  = (const float*)d_in[9];
    const float* gb1  = (const float*)d_in[10];
    const float* gW2  = (const float*)d_in[11];
    const float* gb2  = (const float*)d_in[12];
    const float* Ww   = (const float*)d_in[13];
    const float* Wb   = (const float*)d_in[14];
    const float* bng  = (const float*)d_in[15];
    const float* bnb  = (const float*)d_in[16];
    const float* Mw   = (const float*)d_in[17];
    const float* Mb   = (const float*)d_in[18];

    float* outLS = (float*)d_out;
    float* hid   = (float*)d_out + NN * COUTc;

    k_setup<<<EE + 2, 256>>>(eW1, eb1, eW2, eb2, La, gW1, gb1, gW2, gb2);
    k_expert<<<dim3(28, EE), 256>>>(U, eW3, eb3);
    k_mma_utx<<<dim3(4, 2, NSPLIT), 256>>>(U, X);
    k_pq<<<dim3(25, 2), 128>>>(Ww, Wb);
    k_mma_hid<<<dim3(2, 64), 256>>>(U, hid);
    k_head<<<128, 256>>>(hid, bng, bnb, Mw, Mb, outLS);
}